// round 13
// baseline (speedup 1.0000x reference)
#include <cuda_runtime.h>
#include <cuda_fp16.h>

#define BATCH  512
#define TSTEPS 256
#define IDIM   32
#define HDIM   128
#define GDIM   512                    // 4*H
#define MROWS  (BATCH * TSTEPS)       // 131072

typedef unsigned long long ull;

// ---------------- scratch (static device globals: allocation-free) ----------
__device__ __half g_xg[(size_t)MROWS * GDIM];   // 128 MB fp16, xg1
__device__ __half g_h0[(size_t)MROWS * HDIM];   // 32 MB fp16, layer-0 hidden
__device__ float  g_h1last[BATCH * HDIM];       // last hidden of layer 1
__device__ __half g_whh[2 * GDIM * HDIM];       // fp16 w_hh0, w_hh1
__device__ __half g_wih0[GDIM * IDIM];          // fp16 w_ih0
__device__ __half g_wih1[GDIM * HDIM];          // fp16 w_ih1
__device__ __half g_xh[(size_t)BATCH * TSTEPS * IDIM];  // fp16 x
__device__ float  g_bsum0[GDIM], g_bsum1[GDIM]; // b_ih + b_hh

// ---------------- fast transcendentals ---------------------------------------
__device__ __forceinline__ float ex2f(float x) {
    float y; asm("ex2.approx.f32 %0, %1;" : "=f"(y) : "f"(x)); return y;
}
__device__ __forceinline__ float rcpf(float x) {
    float y; asm("rcp.approx.f32 %0, %1;" : "=f"(y) : "f"(x)); return y;
}
__device__ __forceinline__ float sigmf(float x) {
    return rcpf(1.0f + ex2f(-1.4426950408889634f * x));
}
__device__ __forceinline__ float tanhf_(float x) {
    return 2.0f * sigmf(2.0f * x) - 1.0f;
}

// ---------------- HMMA m16n8k16 fp16->fp32 -----------------------------------
__device__ __forceinline__ void hmma(float* c, const unsigned* a, unsigned b0, unsigned b1) {
    asm volatile("mma.sync.aligned.m16n8k16.row.col.f32.f16.f16.f32 "
        "{%0,%1,%2,%3}, {%4,%5,%6,%7}, {%8,%9}, {%0,%1,%2,%3};"
        : "+f"(c[0]), "+f"(c[1]), "+f"(c[2]), "+f"(c[3])
        : "r"(a[0]), "r"(a[1]), "r"(a[2]), "r"(a[3]), "r"(b0), "r"(b1));
}

// Gate-permuted A-fragments: warp owns all 4 gates of u-band u0..u0+7.
// mt=0 -> {i (+0), f (+128)}, mt=1 -> {g (+256), o (+384)}.
// After MMA: acc[0][j]=i(u, b=2tg+j), acc[0][2+j]=f, acc[1][j]=g, acc[1][2+j]=o.
template<int LD>
__device__ __forceinline__ void load_afrag_perm(unsigned afr[2][LD == 32 ? 2 : 8][4],
                                                const __half* W, int u0, int g, int tg) {
    const int NKT = (LD == 32) ? 2 : 8;
    #pragma unroll
    for (int mt = 0; mt < 2; mt++) {
        int rA = (mt * 256)       + u0 + g;   // i or g block
        int rB = (mt * 256 + 128) + u0 + g;   // f or o block
        #pragma unroll
        for (int kt = 0; kt < NKT; kt++) {
            int kb = kt * 16 + tg * 2;
            afr[mt][kt][0] = *(const unsigned*)&W[rA * LD + kb];
            afr[mt][kt][1] = *(const unsigned*)&W[rB * LD + kb];
            afr[mt][kt][2] = *(const unsigned*)&W[rA * LD + kb + 8];
            afr[mt][kt][3] = *(const unsigned*)&W[rB * LD + kb + 8];
        }
    }
}

// ---------------- K0: fp16 conversions + bias sums ---------------------------
__global__ void k_convert(const float* __restrict__ x,
                          const float* __restrict__ w_ih0, const float* __restrict__ w_hh0,
                          const float* __restrict__ b_ih0, const float* __restrict__ b_hh0,
                          const float* __restrict__ w_ih1, const float* __restrict__ w_hh1,
                          const float* __restrict__ b_ih1, const float* __restrict__ b_hh1) {
    int i = blockIdx.x * blockDim.x + threadIdx.x;
    if (i < BATCH * TSTEPS * IDIM) g_xh[i] = __float2half(x[i]);
    if (i < GDIM * HDIM) {
        g_whh[i]               = __float2half(w_hh0[i]);
        g_whh[GDIM * HDIM + i] = __float2half(w_hh1[i]);
        g_wih1[i]              = __float2half(w_ih1[i]);
    }
    if (i < GDIM * IDIM) g_wih0[i] = __float2half(w_ih0[i]);
    if (i < GDIM) {
        g_bsum0[i] = b_ih0[i] + b_hh0[i];
        g_bsum1[i] = b_ih1[i] + b_hh1[i];
    }
}

// ---------------- K1: layer-0 fused (input GEMM + recurrence) ----------------
// 128 CTAs x 512 threads; CTA owns 4 batch elems (MMA n-cols 4..7 ride on
// zeros). Gate-permuted fragments; elementwise entirely in MMA registers;
// one barrier per step; split accumulators to shorten the HMMA dep chain.
__global__ __launch_bounds__(512, 1) void k_rec0() {
    extern __shared__ char smr[];
    __half* xtile = (__half*)smr;                   // [ts][8][40] fp16, 163840 B
    __half* hT    = (__half*)(smr + 163840);        // [2][8][136] fp16, 4352 B

    const int t = threadIdx.x;
    const int warp = t >> 5, lane = t & 31;
    const int g = lane >> 2, tg = lane & 3;
    const int u0 = warp * 8, u = u0 + g;
    const size_t cta_b = (size_t)blockIdx.x * 4;

    unsigned ah[2][8][4], ax[2][2][4];
    load_afrag_perm<HDIM>(ah, g_whh, u0, g, tg);
    load_afrag_perm<IDIM>(ax, g_wih0, u0, g, tg);

    // zero x tile (rows b=4..7 stay zero) and both h buffers
    uint4 zz; zz.x = zz.y = zz.z = zz.w = 0u;
    uint4* xd = (uint4*)xtile;                      // row pitch = 5 uint4
    for (int i = t; i < 256 * 8 * 5; i += 512) xd[i] = zz;
    for (int i = t; i < 2 * 8 * 136 / 8; i += 512) ((uint4*)hT)[i] = zz;
    __syncthreads();

    // stage x for 4 batches: [b][ts][32] -> xtile[ts][b][40]
    {
        const uint4* xs = (const uint4*)g_xh;
        for (int i = t; i < 256 * 4 * 4; i += 512) {
            int ts = i >> 4, b = (i >> 2) & 3, q = i & 3;
            xd[(ts * 8 + b) * 5 + q] = xs[(cta_b + b) * 1024 + ts * 4 + q];
        }
    }

    const float bi = g_bsum0[u],       bf = g_bsum0[u + 128];
    const float bg = g_bsum0[u + 256], bo = g_bsum0[u + 384];
    float cst[2] = {0.f, 0.f};
    __syncthreads();

    int cur = 0;
    for (int ts = 0; ts < TSTEPS; ts++) {
        float accA[2][4], accB[2][4];
        #pragma unroll
        for (int mt = 0; mt < 2; mt++)
            #pragma unroll
            for (int p = 0; p < 4; p++) { accA[mt][p] = 0.f; accB[mt][p] = 0.f; }

        // x-part (K = 32) -> chain A
        #pragma unroll
        for (int kt = 0; kt < 2; kt++) {
            unsigned b0 = *(const unsigned*)&xtile[(ts * 8 + g) * 40 + kt * 16 + tg * 2];
            unsigned b1 = *(const unsigned*)&xtile[(ts * 8 + g) * 40 + kt * 16 + tg * 2 + 8];
            hmma(accA[0], ax[0][kt], b0, b1);
            hmma(accA[1], ax[1][kt], b0, b1);
        }
        // h-part (K = 128): kt 0..3 -> chain A, kt 4..7 -> chain B
        const __half* hc = hT + cur * (8 * 136);
        #pragma unroll
        for (int kt = 0; kt < 8; kt++) {
            unsigned b0 = *(const unsigned*)&hc[g * 136 + kt * 16 + tg * 2];
            unsigned b1 = *(const unsigned*)&hc[g * 136 + kt * 16 + tg * 2 + 8];
            float* dA = (kt < 4) ? accA[0] : accB[0];
            float* dB = (kt < 4) ? accA[1] : accB[1];
            hmma(dA, ah[0][kt], b0, b1);
            hmma(dB, ah[1][kt], b0, b1);
        }

        // elementwise: cells (u, b=2tg+j) for tg<2 -> b in 0..3
        __half* hn = hT + (cur ^ 1) * (8 * 136);
        if (tg < 2) {
            #pragma unroll
            for (int j = 0; j < 2; j++) {
                int b = 2 * tg + j;
                float gi = sigmf (accA[0][j]     + accB[0][j]     + bi);
                float gf = sigmf (accA[0][2 + j] + accB[0][2 + j] + bf);
                float gg = tanhf_(accA[1][j]     + accB[1][j]     + bg);
                float go = sigmf (accA[1][2 + j] + accB[1][2 + j] + bo);
                cst[j] = gf * cst[j] + gi * gg;
                float h = go * tanhf_(cst[j]);
                hn[b * 136 + u] = __float2half(h);
                g_h0[((cta_b + b) * TSTEPS + ts) * HDIM + u] = __float2half(h);
            }
        }
        __syncthreads();
        cur ^= 1;
    }
}

// ---------------- K2: xg1[M,512] = h0[M,128] @ w_ih1^T + bsum1 (HMMA) --------
__global__ __launch_bounds__(512, 1) void k_gemmh() {
    __shared__ __half atile[2][8 * 136];
    __shared__ __half gtile[8 * 520];
    const int t = threadIdx.x;
    const int warp = t >> 5, lane = t & 31;
    const int g = lane >> 2, tg = lane & 3;
    const size_t row0 = (size_t)blockIdx.x * 128;

    unsigned afr[2][8][4];
    float bb[2][2];
    #pragma unroll
    for (int mt = 0; mt < 2; mt++) {
        int rbase = warp * 32 + mt * 16;
        #pragma unroll
        for (int kt = 0; kt < 8; kt++) {
            int kb = kt * 16 + tg * 2;
            afr[mt][kt][0] = *(const unsigned*)&g_wih1[(rbase + g)     * HDIM + kb];
            afr[mt][kt][1] = *(const unsigned*)&g_wih1[(rbase + g + 8) * HDIM + kb];
            afr[mt][kt][2] = *(const unsigned*)&g_wih1[(rbase + g)     * HDIM + kb + 8];
            afr[mt][kt][3] = *(const unsigned*)&g_wih1[(rbase + g + 8) * HDIM + kb + 8];
        }
        bb[mt][0] = g_bsum1[rbase + g];
        bb[mt][1] = g_bsum1[rbase + g + 8];
    }

    if (t < 128) {
        int r = t >> 4, q = t & 15;
        *(uint4*)&atile[0][r * 136 + q * 8] = *(const uint4*)(g_h0 + (row0 + r) * HDIM + q * 8);
    }
    __syncthreads();

    #pragma unroll 1
    for (int c = 0; c < 16; c++) {
        int buf = c & 1;
        float acc[2][4];
        #pragma unroll
        for (int mt = 0; mt < 2; mt++)
            #pragma unroll
            for (int p = 0; p < 4; p++) acc[mt][p] = 0.f;

        #pragma unroll
        for (int kt = 0; kt < 8; kt++) {
            unsigned b0 = *(const unsigned*)&atile[buf][g * 136 + kt * 16 + tg * 2];
            unsigned b1 = *(const unsigned*)&atile[buf][g * 136 + kt * 16 + tg * 2 + 8];
            hmma(acc[0], afr[0][kt], b0, b1);
            hmma(acc[1], afr[1][kt], b0, b1);
        }

        if (c < 15 && t < 128) {
            int r = t >> 4, q = t & 15;
            *(uint4*)&atile[buf ^ 1][r * 136 + q * 8] =
                *(const uint4*)(g_h0 + (row0 + (c + 1) * 8 + r) * HDIM + q * 8);
        }

        #pragma unroll
        for (int mt = 0; mt < 2; mt++) {
            int r = warp * 32 + mt * 16 + g;
            gtile[(2 * tg)     * 520 + r]     = __float2half(acc[mt][0] + bb[mt][0]);
            gtile[(2 * tg + 1) * 520 + r]     = __float2half(acc[mt][1] + bb[mt][0]);
            gtile[(2 * tg)     * 520 + r + 8] = __float2half(acc[mt][2] + bb[mt][1]);
            gtile[(2 * tg + 1) * 520 + r + 8] = __float2half(acc[mt][3] + bb[mt][1]);
        }
        __syncthreads();

        {
            int n = t >> 6, off = (t & 63) * 8;
            uint4 v = *(uint4*)&gtile[n * 520 + off];
            *(uint4*)(g_xg + (row0 + c * 8 + n) * GDIM + off) = v;
        }
        __syncthreads();
    }
}

// ---------------- K3: layer-1 recurrence (gate-permuted, 128 CTAs) -----------
// 128 CTAs x 512 threads; CTA owns 4 batch elems; xg double-buffered in smem.
__global__ __launch_bounds__(512, 1) void k_rec1() {
    __shared__ __half xs[2][4 * 520];               // 8320 B
    __shared__ __half hT[2][8 * 136];               // 4352 B

    const int t = threadIdx.x;
    const int warp = t >> 5, lane = t & 31;
    const int g = lane >> 2, tg = lane & 3;
    const int u0 = warp * 8, u = u0 + g;
    const size_t cta_b = (size_t)blockIdx.x * 4;

    unsigned ah[2][8][4];
    load_afrag_perm<HDIM>(ah, g_whh + GDIM * HDIM, u0, g, tg);

    uint4 zz; zz.x = zz.y = zz.z = zz.w = 0u;
    for (int i = t; i < 2 * 8 * 136 / 8; i += 512) ((uint4*)hT)[i] = zz;

    // loader role (256 threads): batch lb = t>>6 (0..3), chunk lq = t&63
    const int lb = t >> 6, lq = t & 63;
    const bool loader = (t < 256);
    if (loader)
        *(uint4*)&xs[0][lb * 520 + lq * 8] =
            *(const uint4*)(g_xg + ((cta_b + lb) * TSTEPS) * GDIM + lq * 8);

    float cst[2] = {0.f, 0.f};
    __syncthreads();

    int cur = 0;
    for (int ts = 0; ts < TSTEPS; ts++) {
        // prefetch next step's xg (coalesced; hidden under the HMMA chain)
        uint4 xpre = zz;
        if (loader && ts < TSTEPS - 1)
            xpre = *(const uint4*)(g_xg + ((cta_b + lb) * TSTEPS + ts + 1) * GDIM + lq * 8);

        float accA[2][4], accB[2][4];
        #pragma unroll
        for (int mt = 0; mt < 2; mt++)
            #pragma unroll
            for (int p = 0; p < 4; p++) { accA[mt][p] = 0.f; accB[mt][p] = 0.f; }

        const __half* hc = hT[cur];
        #pragma unroll
        for (int kt = 0; kt < 8; kt++) {
            unsigned b0 = *(const unsigned*)&hc[g * 136 + kt * 16 + tg * 2];
            unsigned b1 = *(const unsigned*)&hc[g * 136 + kt * 16 + tg * 2 + 8];
            float* dA = (kt < 4) ? accA[0] : accB[0];
            float* dB = (kt < 4) ? accA[1] : accB[1];
            hmma(dA, ah[0][kt], b0, b1);
            hmma(dB, ah[1][kt], b0, b1);
        }

        if (loader)
            *(uint4*)&xs[cur ^ 1][lb * 520 + lq * 8] = xpre;

        // elementwise: cells (u, b=2tg+j) for tg<2
        const __half* xc = xs[cur];
        __half* hn = hT[cur ^ 1];
        if (tg < 2) {
            #pragma unroll
            for (int j = 0; j < 2; j++) {
                int b = 2 * tg + j;
                const __half* xb = &xc[b * 520];
                float gi = sigmf (accA[0][j]     + accB[0][j]     + __half2float(xb[u]));
                float gf = sigmf (accA[0][2 + j] + accB[0][2 + j] + __half2float(xb[u + 128]));
                float gg = tanhf_(accA[1][j]     + accB[1][j]     + __half2float(xb[u + 256]));
                float go = sigmf (accA[1][2 + j] + accB[1][2 + j] + __half2float(xb[u + 384]));
                cst[j] = gf * cst[j] + gi * gg;
                float h = go * tanhf_(cst[j]);
                hn[b * 136 + u] = __float2half(h);
                if (ts == TSTEPS - 1)
                    g_h1last[(cta_b + b) * HDIM + u] = h;
            }
        }
        __syncthreads();
        cur ^= 1;
    }
}

// ---------------- K4: FC head -------------------------------------------------
__global__ void k_fc(const float* __restrict__ w1, const float* __restrict__ b1,
                     const float* __restrict__ w2, const float* __restrict__ b2,
                     float* __restrict__ out) {
    __shared__ float red[2];
    int b = blockIdx.x, j = threadIdx.x;   // 64 threads
    const float* hv = g_h1last + b * HDIM;
    const float* wr = w1 + j * HDIM;
    float acc = b1[j];
    #pragma unroll 4
    for (int k = 0; k < HDIM; k++) acc += hv[k] * wr[k];
    float z = fmaxf(acc, 0.0f) * w2[j];
    #pragma unroll
    for (int off = 16; off > 0; off >>= 1) z += __shfl_down_sync(0xffffffffu, z, off);
    if ((j & 31) == 0) red[j >> 5] = z;
    __syncthreads();
    if (j == 0) out[b] = red[0] + red[1] + b2[0];
}

// ---------------- launch -----------------------------------------------------
extern "C" void kernel_launch(void* const* d_in, const int* in_sizes, int n_in,
                              void* d_out, int out_size) {
    const float* x     = (const float*)d_in[0];
    const float* w_ih0 = (const float*)d_in[1];
    const float* w_hh0 = (const float*)d_in[2];
    const float* b_ih0 = (const float*)d_in[3];
    const float* b_hh0 = (const float*)d_in[4];
    const float* w_ih1 = (const float*)d_in[5];
    const float* w_hh1 = (const float*)d_in[6];
    const float* b_ih1 = (const float*)d_in[7];
    const float* b_hh1 = (const float*)d_in[8];
    const float* fc1_w = (const float*)d_in[9];
    const float* fc1_b = (const float*)d_in[10];
    const float* fc2_w = (const float*)d_in[11];
    const float* fc2_b = (const float*)d_in[12];
    float* out = (float*)d_out;

    const int smem_rec0 = 163840 + 4352;           // 168192
    cudaFuncSetAttribute(k_rec0, cudaFuncAttributeMaxDynamicSharedMemorySize, smem_rec0);

    k_convert<<<(BATCH * TSTEPS * IDIM + 255) / 256, 256>>>(
        x, w_ih0, w_hh0, b_ih0, b_hh0, w_ih1, w_hh1, b_ih1, b_hh1);
    // layer 0: fused input-GEMM + recurrence (writes g_h0), 128 CTAs
    k_rec0<<<BATCH / 4, 512, smem_rec0>>>();
    // xg1 = h0 @ w_ih1^T + bsum1 (writes g_xg)
    k_gemmh<<<1024, 512>>>();
    // layer-1 recurrence (writes g_h1last), 128 CTAs
    k_rec1<<<BATCH / 4, 512>>>();
    // FC head
    k_fc<<<BATCH, 64>>>(fc1_w, fc1_b, fc2_w, fc2_b, out);
}

// round 14
// speedup vs baseline: 1.1594x; 1.1594x over previous
#include <cuda_runtime.h>
#include <cuda_fp16.h>

#define BATCH  512
#define TSTEPS 256
#define IDIM   32
#define HDIM   128
#define GDIM   512                    // 4*H
#define MROWS  (BATCH * TSTEPS)       // 131072

typedef unsigned long long ull;

// ---------------- scratch (static device globals: allocation-free) ----------
__device__ __half g_xg[(size_t)MROWS * GDIM];   // 128 MB fp16, xg1
__device__ __half g_h0[(size_t)MROWS * HDIM];   // 32 MB fp16, layer-0 hidden
__device__ float  g_h1last[BATCH * HDIM];       // last hidden of layer 1
__device__ __half g_whh[2 * GDIM * HDIM];       // fp16 w_hh0, w_hh1
__device__ __half g_wih0[GDIM * IDIM];          // fp16 w_ih0
__device__ __half g_wih1[GDIM * HDIM];          // fp16 w_ih1
__device__ __half g_xh[(size_t)BATCH * TSTEPS * IDIM];  // fp16 x
__device__ float  g_bsum0[GDIM], g_bsum1[GDIM]; // b_ih + b_hh

// ---------------- fast transcendentals ---------------------------------------
__device__ __forceinline__ float ex2f(float x) {
    float y; asm("ex2.approx.f32 %0, %1;" : "=f"(y) : "f"(x)); return y;
}
__device__ __forceinline__ float rcpf(float x) {
    float y; asm("rcp.approx.f32 %0, %1;" : "=f"(y) : "f"(x)); return y;
}
__device__ __forceinline__ float sigmf(float x) {
    return rcpf(1.0f + ex2f(-1.4426950408889634f * x));
}
__device__ __forceinline__ float tanhf_(float x) {
    return 2.0f * sigmf(2.0f * x) - 1.0f;
}

// ---------------- HMMA m16n8k16 fp16->fp32 -----------------------------------
__device__ __forceinline__ void hmma(float* c, const unsigned* a, unsigned b0, unsigned b1) {
    asm volatile("mma.sync.aligned.m16n8k16.row.col.f32.f16.f16.f32 "
        "{%0,%1,%2,%3}, {%4,%5,%6,%7}, {%8,%9}, {%0,%1,%2,%3};"
        : "+f"(c[0]), "+f"(c[1]), "+f"(c[2]), "+f"(c[3])
        : "r"(a[0]), "r"(a[1]), "r"(a[2]), "r"(a[3]), "r"(b0), "r"(b1));
}

// Gate-permuted A-fragments: warp owns all 4 gates of u-band u0..u0+7.
// mt=0 -> {i (+0), f (+128)}, mt=1 -> {g (+256), o (+384)}.
// After MMA: acc[0][j]=i(u, b=2tg+j), acc[0][2+j]=f, acc[1][j]=g, acc[1][2+j]=o.
template<int LD>
__device__ __forceinline__ void load_afrag_perm(unsigned afr[2][LD == 32 ? 2 : 8][4],
                                                const __half* W, int u0, int g, int tg) {
    const int NKT = (LD == 32) ? 2 : 8;
    #pragma unroll
    for (int mt = 0; mt < 2; mt++) {
        int rA = (mt * 256)       + u0 + g;   // i or g block
        int rB = (mt * 256 + 128) + u0 + g;   // f or o block
        #pragma unroll
        for (int kt = 0; kt < NKT; kt++) {
            int kb = kt * 16 + tg * 2;
            afr[mt][kt][0] = *(const unsigned*)&W[rA * LD + kb];
            afr[mt][kt][1] = *(const unsigned*)&W[rB * LD + kb];
            afr[mt][kt][2] = *(const unsigned*)&W[rA * LD + kb + 8];
            afr[mt][kt][3] = *(const unsigned*)&W[rB * LD + kb + 8];
        }
    }
}

// ---------------- K0: fp16 conversions + bias sums ---------------------------
__global__ void k_convert(const float* __restrict__ x,
                          const float* __restrict__ w_ih0, const float* __restrict__ w_hh0,
                          const float* __restrict__ b_ih0, const float* __restrict__ b_hh0,
                          const float* __restrict__ w_ih1, const float* __restrict__ w_hh1,
                          const float* __restrict__ b_ih1, const float* __restrict__ b_hh1) {
    int i = blockIdx.x * blockDim.x + threadIdx.x;
    if (i < BATCH * TSTEPS * IDIM) g_xh[i] = __float2half(x[i]);
    if (i < GDIM * HDIM) {
        g_whh[i]               = __float2half(w_hh0[i]);
        g_whh[GDIM * HDIM + i] = __float2half(w_hh1[i]);
        g_wih1[i]              = __float2half(w_ih1[i]);
    }
    if (i < GDIM * IDIM) g_wih0[i] = __float2half(w_ih0[i]);
    if (i < GDIM) {
        g_bsum0[i] = b_ih0[i] + b_hh0[i];
        g_bsum1[i] = b_ih1[i] + b_hh1[i];
    }
}

// Shuffle-redistribute: thread (g,tg) produced cells (u,2tg),(u,2tg+1) in
// (v0,v1); owner mapping b=tg pulls gate[j=tg&1] from lane (lane&~3)|(tg>>1).
__device__ __forceinline__ float gate_to_owner(float v0, float v1, int src, bool j1) {
    float a = __shfl_sync(0xffffffffu, v0, src);
    float b = __shfl_sync(0xffffffffu, v1, src);
    return j1 ? b : a;
}

// ---------------- K1: layer-0 fused (input GEMM + recurrence) ----------------
// 128 CTAs x 512 threads; CTA owns 4 batch elems (MMA n-cols 4..7 ride zeros).
// Gate-permuted fragments; gates stay in registers; shuffle rebalances
// elementwise to exactly 1 cell per lane; one barrier per step.
__global__ __launch_bounds__(512, 1) void k_rec0() {
    extern __shared__ char smr[];
    __half* xtile = (__half*)smr;                   // [ts][8][40] fp16, 163840 B
    __half* hT    = (__half*)(smr + 163840);        // [2][8][136] fp16, 4352 B

    const int t = threadIdx.x;
    const int warp = t >> 5, lane = t & 31;
    const int g = lane >> 2, tg = lane & 3;
    const int u0 = warp * 8, u = u0 + g;
    const size_t cta_b = (size_t)blockIdx.x * 4;

    unsigned ah[2][8][4], ax[2][2][4];
    load_afrag_perm<HDIM>(ah, g_whh, u0, g, tg);
    load_afrag_perm<IDIM>(ax, g_wih0, u0, g, tg);

    // zero x tile (rows b=4..7 stay zero) and both h buffers
    uint4 zz; zz.x = zz.y = zz.z = zz.w = 0u;
    uint4* xd = (uint4*)xtile;                      // row pitch = 5 uint4
    for (int i = t; i < 256 * 8 * 5; i += 512) xd[i] = zz;
    for (int i = t; i < 2 * 8 * 136 / 8; i += 512) ((uint4*)hT)[i] = zz;
    __syncthreads();

    // stage x for 4 batches: [b][ts][32] -> xtile[ts][b][40]
    {
        const uint4* xs = (const uint4*)g_xh;
        for (int i = t; i < 256 * 4 * 4; i += 512) {
            int ts = i >> 4, b = (i >> 2) & 3, q = i & 3;
            xd[(ts * 8 + b) * 5 + q] = xs[(cta_b + b) * 1024 + ts * 4 + q];
        }
    }

    const float bi = g_bsum0[u],       bf = g_bsum0[u + 128];
    const float bg = g_bsum0[u + 256], bo = g_bsum0[u + 384];
    const int  src = (lane & ~3) | (tg >> 1);
    const bool j1  = tg & 1;
    float cst = 0.f;
    __syncthreads();

    int cur = 0;
    for (int ts = 0; ts < TSTEPS; ts++) {
        float accA[2][4], accB[2][4];
        #pragma unroll
        for (int mt = 0; mt < 2; mt++)
            #pragma unroll
            for (int p = 0; p < 4; p++) { accA[mt][p] = 0.f; accB[mt][p] = 0.f; }

        // x-part (K = 32) -> chain A
        #pragma unroll
        for (int kt = 0; kt < 2; kt++) {
            unsigned b0 = *(const unsigned*)&xtile[(ts * 8 + g) * 40 + kt * 16 + tg * 2];
            unsigned b1 = *(const unsigned*)&xtile[(ts * 8 + g) * 40 + kt * 16 + tg * 2 + 8];
            hmma(accA[0], ax[0][kt], b0, b1);
            hmma(accA[1], ax[1][kt], b0, b1);
        }
        // h-part (K = 128): kt 0..3 -> chain A, kt 4..7 -> chain B
        const __half* hc = hT + cur * (8 * 136);
        #pragma unroll
        for (int kt = 0; kt < 8; kt++) {
            unsigned b0 = *(const unsigned*)&hc[g * 136 + kt * 16 + tg * 2];
            unsigned b1 = *(const unsigned*)&hc[g * 136 + kt * 16 + tg * 2 + 8];
            float* dA = (kt < 4) ? accA[0] : accB[0];
            float* dB = (kt < 4) ? accA[1] : accB[1];
            hmma(dA, ah[0][kt], b0, b1);
            hmma(dB, ah[1][kt], b0, b1);
        }

        // sum chains (both j), shuffle to owner lane (b = tg), 1 cell/lane
        float vi = gate_to_owner(accA[0][0] + accB[0][0], accA[0][1] + accB[0][1], src, j1);
        float vf = gate_to_owner(accA[0][2] + accB[0][2], accA[0][3] + accB[0][3], src, j1);
        float vg = gate_to_owner(accA[1][0] + accB[1][0], accA[1][1] + accB[1][1], src, j1);
        float vo = gate_to_owner(accA[1][2] + accB[1][2], accA[1][3] + accB[1][3], src, j1);

        __half* hn = hT + (cur ^ 1) * (8 * 136);
        {
            float gi = sigmf (vi + bi);
            float gf = sigmf (vf + bf);
            float gg = tanhf_(vg + bg);
            float go = sigmf (vo + bo);
            cst = gf * cst + gi * gg;
            float h = go * tanhf_(cst);
            hn[tg * 136 + u] = __float2half(h);
            g_h0[((cta_b + tg) * TSTEPS + ts) * HDIM + u] = __float2half(h);
        }
        __syncthreads();
        cur ^= 1;
    }
}

// ---------------- K2: xg1[M,512] = h0[M,128] @ w_ih1^T + bsum1 (HMMA) --------
__global__ __launch_bounds__(512, 1) void k_gemmh() {
    __shared__ __half atile[2][8 * 136];
    __shared__ __half gtile[8 * 520];
    const int t = threadIdx.x;
    const int warp = t >> 5, lane = t & 31;
    const int g = lane >> 2, tg = lane & 3;
    const size_t row0 = (size_t)blockIdx.x * 128;

    unsigned afr[2][8][4];
    float bb[2][2];
    #pragma unroll
    for (int mt = 0; mt < 2; mt++) {
        int rbase = warp * 32 + mt * 16;
        #pragma unroll
        for (int kt = 0; kt < 8; kt++) {
            int kb = kt * 16 + tg * 2;
            afr[mt][kt][0] = *(const unsigned*)&g_wih1[(rbase + g)     * HDIM + kb];
            afr[mt][kt][1] = *(const unsigned*)&g_wih1[(rbase + g + 8) * HDIM + kb];
            afr[mt][kt][2] = *(const unsigned*)&g_wih1[(rbase + g)     * HDIM + kb + 8];
            afr[mt][kt][3] = *(const unsigned*)&g_wih1[(rbase + g + 8) * HDIM + kb + 8];
        }
        bb[mt][0] = g_bsum1[rbase + g];
        bb[mt][1] = g_bsum1[rbase + g + 8];
    }

    if (t < 128) {
        int r = t >> 4, q = t & 15;
        *(uint4*)&atile[0][r * 136 + q * 8] = *(const uint4*)(g_h0 + (row0 + r) * HDIM + q * 8);
    }
    __syncthreads();

    #pragma unroll 1
    for (int c = 0; c < 16; c++) {
        int buf = c & 1;
        float acc[2][4];
        #pragma unroll
        for (int mt = 0; mt < 2; mt++)
            #pragma unroll
            for (int p = 0; p < 4; p++) acc[mt][p] = 0.f;

        #pragma unroll
        for (int kt = 0; kt < 8; kt++) {
            unsigned b0 = *(const unsigned*)&atile[buf][g * 136 + kt * 16 + tg * 2];
            unsigned b1 = *(const unsigned*)&atile[buf][g * 136 + kt * 16 + tg * 2 + 8];
            hmma(acc[0], afr[0][kt], b0, b1);
            hmma(acc[1], afr[1][kt], b0, b1);
        }

        if (c < 15 && t < 128) {
            int r = t >> 4, q = t & 15;
            *(uint4*)&atile[buf ^ 1][r * 136 + q * 8] =
                *(const uint4*)(g_h0 + (row0 + (c + 1) * 8 + r) * HDIM + q * 8);
        }

        #pragma unroll
        for (int mt = 0; mt < 2; mt++) {
            int r = warp * 32 + mt * 16 + g;
            gtile[(2 * tg)     * 520 + r]     = __float2half(acc[mt][0] + bb[mt][0]);
            gtile[(2 * tg + 1) * 520 + r]     = __float2half(acc[mt][1] + bb[mt][0]);
            gtile[(2 * tg)     * 520 + r + 8] = __float2half(acc[mt][2] + bb[mt][1]);
            gtile[(2 * tg + 1) * 520 + r + 8] = __float2half(acc[mt][3] + bb[mt][1]);
        }
        __syncthreads();

        {
            int n = t >> 6, off = (t & 63) * 8;
            uint4 v = *(uint4*)&gtile[n * 520 + off];
            *(uint4*)(g_xg + (row0 + c * 8 + n) * GDIM + off) = v;
        }
        __syncthreads();
    }
}

// ---------------- K3: layer-1 recurrence (gate-permuted + shuffle) -----------
// 128 CTAs x 512 threads; CTA owns 4 batch elems; xg double-buffered in smem.
__global__ __launch_bounds__(512, 1) void k_rec1() {
    __shared__ __half xs[2][4 * 520];               // 8320 B
    __shared__ __half hT[2][8 * 136];               // 4352 B

    const int t = threadIdx.x;
    const int warp = t >> 5, lane = t & 31;
    const int g = lane >> 2, tg = lane & 3;
    const int u0 = warp * 8, u = u0 + g;
    const size_t cta_b = (size_t)blockIdx.x * 4;

    unsigned ah[2][8][4];
    load_afrag_perm<HDIM>(ah, g_whh + GDIM * HDIM, u0, g, tg);

    uint4 zz; zz.x = zz.y = zz.z = zz.w = 0u;
    for (int i = t; i < 2 * 8 * 136 / 8; i += 512) ((uint4*)hT)[i] = zz;

    // loader role (256 threads): batch lb = t>>6 (0..3), chunk lq = t&63
    const int lb = t >> 6, lq = t & 63;
    const bool loader = (t < 256);
    if (loader)
        *(uint4*)&xs[0][lb * 520 + lq * 8] =
            *(const uint4*)(g_xg + ((cta_b + lb) * TSTEPS) * GDIM + lq * 8);

    const int  src = (lane & ~3) | (tg >> 1);
    const bool j1  = tg & 1;
    float cst = 0.f;
    __syncthreads();

    int cur = 0;
    for (int ts = 0; ts < TSTEPS; ts++) {
        // prefetch next step's xg (coalesced; hidden under the HMMA chain)
        uint4 xpre = zz;
        if (loader && ts < TSTEPS - 1)
            xpre = *(const uint4*)(g_xg + ((cta_b + lb) * TSTEPS + ts + 1) * GDIM + lq * 8);

        float accA[2][4], accB[2][4];
        #pragma unroll
        for (int mt = 0; mt < 2; mt++)
            #pragma unroll
            for (int p = 0; p < 4; p++) { accA[mt][p] = 0.f; accB[mt][p] = 0.f; }

        const __half* hc = hT[cur];
        #pragma unroll
        for (int kt = 0; kt < 8; kt++) {
            unsigned b0 = *(const unsigned*)&hc[g * 136 + kt * 16 + tg * 2];
            unsigned b1 = *(const unsigned*)&hc[g * 136 + kt * 16 + tg * 2 + 8];
            float* dA = (kt < 4) ? accA[0] : accB[0];
            float* dB = (kt < 4) ? accA[1] : accB[1];
            hmma(dA, ah[0][kt], b0, b1);
            hmma(dB, ah[1][kt], b0, b1);
        }

        if (loader)
            *(uint4*)&xs[cur ^ 1][lb * 520 + lq * 8] = xpre;

        // shuffle gates to owner lane (b = tg); 1 cell/lane
        float vi = gate_to_owner(accA[0][0] + accB[0][0], accA[0][1] + accB[0][1], src, j1);
        float vf = gate_to_owner(accA[0][2] + accB[0][2], accA[0][3] + accB[0][3], src, j1);
        float vg = gate_to_owner(accA[1][0] + accB[1][0], accA[1][1] + accB[1][1], src, j1);
        float vo = gate_to_owner(accA[1][2] + accB[1][2], accA[1][3] + accB[1][3], src, j1);

        const __half* xb = &xs[cur][tg * 520];
        __half* hn = hT[cur ^ 1];
        {
            float gi = sigmf (vi + __half2float(xb[u]));
            float gf = sigmf (vf + __half2float(xb[u + 128]));
            float gg = tanhf_(vg + __half2float(xb[u + 256]));
            float go = sigmf (vo + __half2float(xb[u + 384]));
            cst = gf * cst + gi * gg;
            float h = go * tanhf_(cst);
            hn[tg * 136 + u] = __float2half(h);
            if (ts == TSTEPS - 1)
                g_h1last[(cta_b + tg) * HDIM + u] = h;
        }
        __syncthreads();
        cur ^= 1;
    }
}

// ---------------- K4: FC head -------------------------------------------------
__global__ void k_fc(const float* __restrict__ w1, const float* __restrict__ b1,
                     const float* __restrict__ w2, const float* __restrict__ b2,
                     float* __restrict__ out) {
    __shared__ float red[2];
    int b = blockIdx.x, j = threadIdx.x;   // 64 threads
    const float* hv = g_h1last + b * HDIM;
    const float* wr = w1 + j * HDIM;
    float acc = b1[j];
    #pragma unroll 4
    for (int k = 0; k < HDIM; k++) acc += hv[k] * wr[k];
    float z = fmaxf(acc, 0.0f) * w2[j];
    #pragma unroll
    for (int off = 16; off > 0; off >>= 1) z += __shfl_down_sync(0xffffffffu, z, off);
    if ((j & 31) == 0) red[j >> 5] = z;
    __syncthreads();
    if (j == 0) out[b] = red[0] + red[1] + b2[0];
}

// ---------------- launch -----------------------------------------------------
extern "C" void kernel_launch(void* const* d_in, const int* in_sizes, int n_in,
                              void* d_out, int out_size) {
    const float* x     = (const float*)d_in[0];
    const float* w_ih0 = (const float*)d_in[1];
    const float* w_hh0 = (const float*)d_in[2];
    const float* b_ih0 = (const float*)d_in[3];
    const float* b_hh0 = (const float*)d_in[4];
    const float* w_ih1 = (const float*)d_in[5];
    const float* w_hh1 = (const float*)d_in[6];
    const float* b_ih1 = (const float*)d_in[7];
    const float* b_hh1 = (const float*)d_in[8];
    const float* fc1_w = (const float*)d_in[9];
    const float* fc1_b = (const float*)d_in[10];
    const float* fc2_w = (const float*)d_in[11];
    const float* fc2_b = (const float*)d_in[12];
    float* out = (float*)d_out;

    const int smem_rec0 = 163840 + 4352;           // 168192
    cudaFuncSetAttribute(k_rec0, cudaFuncAttributeMaxDynamicSharedMemorySize, smem_rec0);

    k_convert<<<(BATCH * TSTEPS * IDIM + 255) / 256, 256>>>(
        x, w_ih0, w_hh0, b_ih0, b_hh0, w_ih1, w_hh1, b_ih1, b_hh1);
    // layer 0: fused input-GEMM + recurrence (writes g_h0), 128 CTAs
    k_rec0<<<BATCH / 4, 512, smem_rec0>>>();
    // xg1 = h0 @ w_ih1^T + bsum1 (writes g_xg)
    k_gemmh<<<1024, 512>>>();
    // layer-1 recurrence (writes g_h1last), 128 CTAs
    k_rec1<<<BATCH / 4, 512>>>();
    // FC head
    k_fc<<<BATCH, 64>>>(fc1_w, fc1_b, fc2_w, fc2_b, out);
}